// round 17
// baseline (speedup 1.0000x reference)
#include <cuda_runtime.h>
#include <cuda_fp16.h>
#include <cstdint>

#define B_SZ 16
#define D_DIM 128
#define T_SZ 4096
#define KCODES 1024
#define NVEC (B_SZ * T_SZ)
#define ROWS 128
#define NCTA (NVEC / ROWS)
#define NTHR 256
#define CAPR 8
#define MARGIN 2.5f

#define OFF_Q 1
#define OFF_PERP (1 + B_SZ * D_DIM * T_SZ)
#define OFF_IDX (2 + B_SZ * D_DIM * T_SZ)

__device__ float g_cnorm[KCODES];
__device__ int g_chh[8 * 64 * 2 * 64];   // [chunk][kpair][half][tc*4+p] half2-packed codes
__device__ float g_counts[KCODES];
__device__ float g_loss;

// dynamic smem offsets (base 1024-aligned)
#define SO_XH 0u        // 64 k x 2 h x 16 tr x 16B = 32768
#define SO_CH 32768u    // 32768 (single-buffered code chunk)
#define SO_XF 65536u    // 128 x 129 fp32 = 66048
#define SO_CN 131584u   // 1024 fp32
#define SO_CAND 135680u // 256 thr x 8 rows x 8 u16 = 32768
#define SO_MS 168448u   // 128 x 16 fp32 = 8192
#define SO_MC 176640u   // 128 x 16 int = 8192
#define SO_BI 184832u   // 128 int
#define SO_RED 185344u  // 64
#define SMEM_DYN 186432u

__device__ __forceinline__ uint32_t smem_u32(const void* p) {
    uint32_t a;
    asm("{ .reg .u64 t; cvta.to.shared.u64 t, %1; cvt.u32.u64 %0, t; }" : "=r"(a) : "l"(p));
    return a;
}

union V16 { int4 i; __half2 h[4]; };

__global__ void vq_prep(const float* __restrict__ cb) {
    int j = blockIdx.x, t = threadIdx.x;
    __shared__ float vals[128];
    __shared__ float ws[4];
    float v = cb[j * D_DIM + t];
    vals[t] = v;
    float s = v * v;
#pragma unroll
    for (int o = 16; o; o >>= 1) s += __shfl_xor_sync(0xFFFFFFFFu, s, o);
    if ((t & 31) == 0) ws[t >> 5] = s;
    __syncthreads();
    if (t < 64) {
        __half2 hv = __floats2half2_rn(vals[2 * t], vals[2 * t + 1]);
        int g = j & 7;
        int idx = (((j >> 7) * 64 + t) * 2 + (g >> 2)) * 64 + ((j & 127) >> 3) * 4 + (g & 3);
        g_chh[idx] = *reinterpret_cast<int*>(&hv);
    }
    if (t == 0) {
        g_cnorm[j] = 0.5f * (ws[0] + ws[1] + ws[2] + ws[3]);
        g_counts[j] = 0.0f;
        if (j == 0) g_loss = 0.0f;
    }
}

__global__ __launch_bounds__(NTHR, 1)
void vq_main(const float* __restrict__ in, const float* __restrict__ cb,
             float* __restrict__ out) {
    extern __shared__ char smraw[];
    const int tid = threadIdx.x;
    uint32_t sb_raw = smem_u32(smraw);
    uint32_t sb = (sb_raw + 1023u) & ~1023u;
    char* sm = smraw + (sb - sb_raw);

    float* xf = (float*)(sm + SO_XF);
    float* cn = (float*)(sm + SO_CN);
    unsigned short* cand = (unsigned short*)(sm + SO_CAND);
    float* mS = (float*)(sm + SO_MS);
    int* mC = (int*)(sm + SO_MC);
    int* bi_s = (int*)(sm + SO_BI);
    float* red = (float*)(sm + SO_RED);

    const int bIdx = blockIdx.x >> 5;
    const int t0 = (blockIdx.x & 31) << 7;
    const float* inb = in + (size_t)bIdx * (D_DIM * T_SZ) + t0;

    const int tr = tid & 15, tc = tid >> 4;

    for (int i = tid; i < KCODES; i += NTHR) cn[i] = g_cnorm[i];

    // x tile fp32 (padded) — coalesced over time index j
    for (int i = tid; i < ROWS * D_DIM; i += NTHR) {
        int d = i >> 7, j = i & 127;
        xf[j * 129 + d] = inb[(size_t)d * T_SZ + j];
    }
    __syncthreads();

    // pack x: xh[k][h][tr][p] half2 of dims (2k,2k+1), row = 8tr+4h+p
    for (int e = tid; e < 8192; e += NTHR) {
        int k = e >> 7, rem = e & 127;
        int h = (rem >> 6) & 1, trr = (rem >> 2) & 15, p = rem & 3;
        int row = 8 * trr + 4 * h + p;
        __half2 hv = __floats2half2_rn(xf[row * 129 + 2 * k], xf[row * 129 + 2 * k + 1]);
        *(__half2*)(sm + SO_XH + (uint32_t)(k * 512 + h * 256 + trr * 16 + p * 4)) = hv;
    }

    // prefetch chunk 0 into regs
    int4 R[8];
    {
        const int4* gp = (const int4*)g_chh + tid * 8;
#pragma unroll
        for (int r = 0; r < 8; ++r) R[r] = gp[r];
    }

    unsigned short* candp = cand + tid * 64;
    float bestR[8];
    int cnts[8];
#pragma unroll
    for (int i = 0; i < 8; ++i) { bestR[i] = -3.0e38f; cnts[i] = 0; }

    const uint32_t xb0 = (uint32_t)(tr * 16);
    const uint32_t cb0 = (uint32_t)(tc * 16);

    for (int c = 0; c < 8; ++c) {
        __syncthreads();
        {
            int4* sp = (int4*)(sm + SO_CH + (uint32_t)tid * 128u);
#pragma unroll
            for (int r = 0; r < 8; ++r) sp[r] = R[r];
        }
        __syncthreads();
        if (c < 7) {
            const int4* gp = (const int4*)g_chh + (c + 1) * 2048 + tid * 8;
#pragma unroll
            for (int r = 0; r < 8; ++r) R[r] = gp[r];
        }

        __half2 acc[8][8];
#pragma unroll
        for (int i = 0; i < 8; ++i)
#pragma unroll
            for (int j = 0; j < 8; ++j) acc[i][j] = __floats2half2_rn(0.f, 0.f);

#pragma unroll 4
        for (int k = 0; k < 64; ++k) {
            uint32_t kb = (uint32_t)(k * 512);
            V16 x0, x1, c0, c1;
            x0.i = *(const int4*)(sm + SO_XH + kb + xb0);
            x1.i = *(const int4*)(sm + SO_XH + kb + 256u + xb0);
            c0.i = *(const int4*)(sm + SO_CH + kb + cb0);
            c1.i = *(const int4*)(sm + SO_CH + kb + 256u + cb0);
            __half2 xr[8], cr[8];
#pragma unroll
            for (int p = 0; p < 4; ++p) {
                xr[p] = x0.h[p]; xr[p + 4] = x1.h[p];
                cr[p] = c0.h[p]; cr[p + 4] = c1.h[p];
            }
#pragma unroll
            for (int i = 0; i < 8; ++i)
#pragma unroll
                for (int j = 0; j < 8; ++j)
                    acc[i][j] = __hfma2(xr[i], cr[j], acc[i][j]);
        }

        int gc0 = (c << 7) + (tc << 3);
#pragma unroll
        for (int j = 0; j < 8; ++j) {
            float cnj = cn[gc0 + j];
#pragma unroll
            for (int i = 0; i < 8; ++i) {
                float2 f = __half22float2(acc[i][j]);
                float s = (f.x + f.y) - cnj;
                if (s > bestR[i] - MARGIN) {
                    candp[i * 8 + (cnts[i] & (CAPR - 1))] = (unsigned short)(gc0 + j);
                    ++cnts[i];
                    bestR[i] = fmaxf(bestR[i], s);
                }
            }
        }
    }
    __syncthreads();

    // exact fp32 rescore per thread-row, then per-(row,tc) partials
#pragma unroll 1
    for (int i = 0; i < 8; ++i) {
        int row = 8 * tr + i;
        const float* xr = xf + row * 129;
        float sB = -3.4e38f;
        int cB = KCODES;
        int n = cnts[i] < CAPR ? cnts[i] : CAPR;
        for (int j = 0; j < n; ++j) {
            int code = candp[i * 8 + j];
            const float4* q = (const float4*)(cb + (code << 7));
            float a0 = 0.f, a1 = 0.f, a2 = 0.f, a3 = 0.f;
#pragma unroll
            for (int d = 0; d < 32; ++d) {
                float4 v = __ldg(q + d);
                a0 = fmaf(v.x, xr[4 * d + 0], a0);
                a1 = fmaf(v.y, xr[4 * d + 1], a1);
                a2 = fmaf(v.z, xr[4 * d + 2], a2);
                a3 = fmaf(v.w, xr[4 * d + 3], a3);
            }
            float s = (a0 + a1) + (a2 + a3) - cn[code];
            if (s > sB || (s == sB && code < cB)) { sB = s; cB = code; }
        }
        mS[row * 16 + tc] = sB;
        mC[row * 16 + tc] = cB;
    }
    __syncthreads();

    if (tid < 128) {
        float sB = mS[tid * 16];
        int cB = mC[tid * 16];
#pragma unroll 1
        for (int g = 1; g < 16; ++g) {
            float s = mS[tid * 16 + g];
            int cc = mC[tid * 16 + g];
            if (s > sB || (s == sB && cc < cB)) { sB = s; cB = cc; }
        }
        bi_s[tid] = cB;
        out[OFF_IDX + (size_t)bIdx * T_SZ + t0 + tid] = (float)cB;
        atomicAdd(&g_counts[cB], 1.0f);
    }
    __syncthreads();

    // gather selected codes into xf (overwrite x), accumulate loss
    float lpart = 0.f;
    for (int i = tid; i < ROWS * 32; i += NTHR) {
        int rw = i >> 5, c4 = i & 31;
        int code = bi_s[rw];
        float4 q = __ldg((const float4*)(cb + (code << 7)) + c4);
        float* xp = &xf[rw * 129 + (c4 << 2)];
        float d0 = q.x - xp[0], d1 = q.y - xp[1], d2 = q.z - xp[2], d3 = q.w - xp[3];
        lpart += d0 * d0 + d1 * d1 + d2 * d2 + d3 * d3;
        xp[0] = q.x; xp[1] = q.y; xp[2] = q.z; xp[3] = q.w;
    }
#pragma unroll
    for (int o = 16; o; o >>= 1) lpart += __shfl_xor_sync(0xFFFFFFFFu, lpart, o);
    if ((tid & 31) == 0) red[tid >> 5] = lpart;
    __syncthreads();
    if (tid == 0) {
        float s = 0.f;
        for (int q = 0; q < 8; ++q) s += red[q];
        atomicAdd(&g_loss, s);
    }

    // transposed coalesced quantized write
    for (int i = tid; i < ROWS * D_DIM; i += NTHR) {
        int d = i >> 7, j = i & 127;
        out[OFF_Q + (size_t)bIdx * (D_DIM * T_SZ) + (size_t)d * T_SZ + t0 + j] =
            xf[j * 129 + d];
    }
}

__global__ void vq_fin(float* __restrict__ out) {
    __shared__ float sh[256];
    int t = threadIdx.x;
    float h = 0.f;
    for (int k = t; k < KCODES; k += 256) {
        float p = g_counts[k] * (1.0f / (float)NVEC);
        h += p * logf(p + 1e-10f);
    }
    sh[t] = h;
    __syncthreads();
    for (int o = 128; o; o >>= 1) {
        if (t < o) sh[t] += sh[t + o];
        __syncthreads();
    }
    if (t == 0) {
        out[0] = 0.25f * g_loss / (float)(B_SZ * D_DIM * T_SZ);
        out[OFF_PERP] = expf(-sh[0]);
    }
}

extern "C" void kernel_launch(void* const* d_in, const int* in_sizes, int n_in,
                              void* d_out, int out_size) {
    const float* in = (const float*)d_in[0];
    const float* cb = (const float*)d_in[1];
    if (n_in >= 2 && in_sizes[0] == KCODES * D_DIM) {
        const float* t = in; in = cb; cb = t;
    }
    float* out = (float*)d_out;
    cudaFuncSetAttribute(vq_main, cudaFuncAttributeMaxDynamicSharedMemorySize, SMEM_DYN);
    vq_prep<<<KCODES, 128>>>(cb);
    vq_main<<<NCTA, NTHR, SMEM_DYN>>>(in, cb, out);
    vq_fin<<<1, 256>>>(out);
}